// round 1
// baseline (speedup 1.0000x reference)
#include <cuda_runtime.h>

#define N_NODES 100000
#define N_EDGES 300000
#define FULL 0xffffffffu

// Scratch (device globals — no allocation allowed)
__device__ float g_agg1[N_NODES * 32];
__device__ float g_agg2[N_NODES * 32];
__device__ float g_h1  [N_NODES * 32];
__device__ float g_u0  [N_NODES * 32];
__device__ float g_u1  [N_NODES * 32];
__device__ float g_u2  [N_NODES * 32];

// ---------------------------------------------------------------------------
// Zero the two aggregation buffers
// ---------------------------------------------------------------------------
__global__ void zero_kernel() {
    int idx = blockIdx.x * blockDim.x + threadIdx.x;
    int stride = gridDim.x * blockDim.x;
    const int total = N_NODES * 32;
    for (int i = idx; i < total; i += stride) {
        g_agg1[i] = 0.0f;
        g_agg2[i] = 0.0f;
    }
}

// ---------------------------------------------------------------------------
// Layer-1 edge messages: one warp per edge, lane = output channel o
// msg[o] = x0*(a0*w[o,0]+a1*w[o,1]+b[o]) + x1*(a0*w[32+o,0]+a1*w[32+o,1]+b[32+o])
// ---------------------------------------------------------------------------
__global__ void edge1_kernel(const float* __restrict__ x,
                             const int*   __restrict__ ei,
                             const float* __restrict__ ea,
                             const float* __restrict__ nn1_w,
                             const float* __restrict__ nn1_b) {
    int e = blockIdx.x * (blockDim.x >> 5) + (threadIdx.x >> 5);
    int o = threadIdx.x & 31;
    if (e >= N_EDGES) return;

    int src = ei[e];
    int dst = ei[N_EDGES + e];
    float a0 = ea[2 * e];
    float a1 = ea[2 * e + 1];
    float x0 = x[2 * src];
    float x1 = x[2 * src + 1];

    float w00 = nn1_w[2 * o];
    float w01 = nn1_w[2 * o + 1];
    float b0  = nn1_b[o];
    float w10 = nn1_w[2 * (32 + o)];
    float w11 = nn1_w[2 * (32 + o) + 1];
    float b1  = nn1_b[32 + o];

    float m = x0 * fmaf(a0, w00, fmaf(a1, w01, b0))
            + x1 * fmaf(a0, w10, fmaf(a1, w11, b1));
    atomicAdd(&g_agg1[dst * 32 + o], m);
}

// ---------------------------------------------------------------------------
// Layer-1 node update + layer-2 per-node precompute:
//   h1 = relu(agg1 + x@root1 + bias1)
//   u0 = h1 @ W0 ; u1 = h1 @ W1 ; u2 = h1 @ B   (from nn2_w/nn2_b)
// one warp per node, lane = channel o; h1 broadcast via shuffle
// ---------------------------------------------------------------------------
__global__ void node1_kernel(const float* __restrict__ x,
                             const float* __restrict__ root1,
                             const float* __restrict__ bias1,
                             const float* __restrict__ nn2_w,
                             const float* __restrict__ nn2_b) {
    __shared__ float sW[3][32][32];   // [k][i][o]  k=0:W0, 1:W1, 2:B
    for (int idx = threadIdx.x; idx < 1024; idx += blockDim.x) {
        int i = idx >> 5;
        int o = idx & 31;
        int row = i * 32 + o;             // row of nn2_w / nn2_b
        sW[0][i][o] = nn2_w[2 * row];
        sW[1][i][o] = nn2_w[2 * row + 1];
        sW[2][i][o] = nn2_b[row];
    }
    __syncthreads();

    int n = blockIdx.x * (blockDim.x >> 5) + (threadIdx.x >> 5);
    int o = threadIdx.x & 31;
    if (n >= N_NODES) return;

    float x0 = x[2 * n];
    float x1 = x[2 * n + 1];
    float h = g_agg1[n * 32 + o]
            + fmaf(x0, root1[o], fmaf(x1, root1[32 + o], bias1[o]));
    h = fmaxf(h, 0.0f);
    g_h1[n * 32 + o] = h;

    float u0 = 0.0f, u1 = 0.0f, u2 = 0.0f;
#pragma unroll
    for (int i = 0; i < 32; i++) {
        float hv = __shfl_sync(FULL, h, i);
        u0 = fmaf(hv, sW[0][i][o], u0);
        u1 = fmaf(hv, sW[1][i][o], u1);
        u2 = fmaf(hv, sW[2][i][o], u2);
    }
    g_u0[n * 32 + o] = u0;
    g_u1[n * 32 + o] = u1;
    g_u2[n * 32 + o] = u2;
}

// ---------------------------------------------------------------------------
// Layer-2 edge messages: msg = a0*u0[src] + a1*u1[src] + u2[src]; scatter to dst
// ---------------------------------------------------------------------------
__global__ void edge2_kernel(const int*   __restrict__ ei,
                             const float* __restrict__ ea) {
    int e = blockIdx.x * (blockDim.x >> 5) + (threadIdx.x >> 5);
    int o = threadIdx.x & 31;
    if (e >= N_EDGES) return;

    int src = ei[e];
    int dst = ei[N_EDGES + e];
    float a0 = ea[2 * e];
    float a1 = ea[2 * e + 1];

    int base = src * 32 + o;
    float m = fmaf(a0, g_u0[base], fmaf(a1, g_u1[base], g_u2[base]));
    atomicAdd(&g_agg2[dst * 32 + o], m);
}

// ---------------------------------------------------------------------------
// Tail: h2 = relu(agg2 + h1@root2 + bias2); h3 = relu(h2@fc1^T + b); out = h3@fc2^T + b
// one warp per node
// ---------------------------------------------------------------------------
__global__ void node2_kernel(const float* __restrict__ root2,
                             const float* __restrict__ bias2,
                             const float* __restrict__ fc1_w,
                             const float* __restrict__ fc1_b,
                             const float* __restrict__ fc2_w,
                             const float* __restrict__ fc2_b,
                             float* __restrict__ out) {
    __shared__ float sR[32][32];    // root2 [i][o]
    __shared__ float sF1[32][32];   // fc1_w transposed: [i][o] = fc1_w[o*32+i]
    __shared__ float sF2[32];
    __shared__ float sB2[32];
    __shared__ float sB1f[32];

    for (int idx = threadIdx.x; idx < 1024; idx += blockDim.x) {
        int i = idx >> 5;
        int o = idx & 31;
        sR[i][o]  = root2[i * 32 + o];
        sF1[i][o] = fc1_w[o * 32 + i];
    }
    if (threadIdx.x < 32) {
        sF2[threadIdx.x]  = fc2_w[threadIdx.x];
        sB2[threadIdx.x]  = bias2[threadIdx.x];
        sB1f[threadIdx.x] = fc1_b[threadIdx.x];
    }
    __syncthreads();

    int n = blockIdx.x * (blockDim.x >> 5) + (threadIdx.x >> 5);
    int o = threadIdx.x & 31;
    if (n >= N_NODES) return;

    float h1v = g_h1[n * 32 + o];
    float h2 = g_agg2[n * 32 + o] + sB2[o];
#pragma unroll
    for (int i = 0; i < 32; i++) {
        float hv = __shfl_sync(FULL, h1v, i);
        h2 = fmaf(hv, sR[i][o], h2);
    }
    h2 = fmaxf(h2, 0.0f);

    float h3 = sB1f[o];
#pragma unroll
    for (int i = 0; i < 32; i++) {
        float hv = __shfl_sync(FULL, h2, i);
        h3 = fmaf(hv, sF1[i][o], h3);
    }
    h3 = fmaxf(h3, 0.0f);

    float p = h3 * sF2[o];
#pragma unroll
    for (int off = 16; off > 0; off >>= 1)
        p += __shfl_xor_sync(FULL, p, off);
    if (o == 0)
        out[n] = p + fc2_b[0];
}

// ---------------------------------------------------------------------------
extern "C" void kernel_launch(void* const* d_in, const int* in_sizes, int n_in,
                              void* d_out, int out_size) {
    const float* x      = (const float*)d_in[0];
    const int*   ei     = (const int*)  d_in[1];
    const float* ea     = (const float*)d_in[2];
    const float* nn1_w  = (const float*)d_in[3];
    const float* nn1_b  = (const float*)d_in[4];
    const float* root1  = (const float*)d_in[5];
    const float* bias1  = (const float*)d_in[6];
    const float* nn2_w  = (const float*)d_in[7];
    const float* nn2_b  = (const float*)d_in[8];
    const float* root2  = (const float*)d_in[9];
    const float* bias2  = (const float*)d_in[10];
    const float* fc1_w  = (const float*)d_in[11];
    const float* fc1_b  = (const float*)d_in[12];
    const float* fc2_w  = (const float*)d_in[13];
    const float* fc2_b  = (const float*)d_in[14];
    float* out = (float*)d_out;

    const int TPB = 256;
    const int WARPS_PER_BLK = TPB / 32;

    zero_kernel<<<592, TPB>>>();

    int eblocks = (N_EDGES + WARPS_PER_BLK - 1) / WARPS_PER_BLK;
    int nblocks = (N_NODES + WARPS_PER_BLK - 1) / WARPS_PER_BLK;

    edge1_kernel<<<eblocks, TPB>>>(x, ei, ea, nn1_w, nn1_b);
    node1_kernel<<<nblocks, TPB>>>(x, root1, bias1, nn2_w, nn2_b);
    edge2_kernel<<<eblocks, TPB>>>(ei, ea);
    node2_kernel<<<nblocks, TPB>>>(root2, bias2, fc1_w, fc1_b,
                                   fc2_w, fc2_b, out);
}

// round 6
// speedup vs baseline: 1.2466x; 1.2466x over previous
#include <cuda_runtime.h>

#define N_NODES 100000
#define N_EDGES 300000
#define FULL 0xffffffffu

// Scratch (device globals — no allocation allowed)
__device__ float g_agg1[N_NODES * 32];
__device__ float g_agg2[N_NODES * 32];
__device__ float g_h1  [N_NODES * 32];
__device__ float g_u0  [N_NODES * 32];
__device__ float g_u1  [N_NODES * 32];
__device__ float g_u2  [N_NODES * 32];

// ---------------------------------------------------------------------------
// Zero both aggregation buffers
// ---------------------------------------------------------------------------
__global__ void zero_kernel() {
    int idx = blockIdx.x * blockDim.x + threadIdx.x;
    int stride = gridDim.x * blockDim.x;
    const int total = N_NODES * 32;
    for (int i = idx; i < total; i += stride) {
        g_agg1[i] = 0.0f;
        g_agg2[i] = 0.0f;
    }
}

// ---------------------------------------------------------------------------
// Layer-1 edge scatter, weights in shared (x is only 2-dim so compute direct):
//   msg[o] = x0*(a0*A0[0][o] + a1*A1[0][o] + B[0][o])
//          + x1*(a0*A0[1][o] + a1*A1[1][o] + B[1][o])
// 8 lanes per edge, 4 channels per lane, red.global.add.v4.f32 scatter.
//   A0[i][o] = nn1_w[2*(i*32+o)], A1[i][o] = nn1_w[2*(i*32+o)+1], B[i][o]=nn1_b[i*32+o]
// ---------------------------------------------------------------------------
__global__ void edge1_kernel(const float* __restrict__ x,
                             const int*   __restrict__ ei,
                             const float* __restrict__ ea,
                             const float* __restrict__ nn1_w,
                             const float* __restrict__ nn1_b) {
    __shared__ float sW[6][32];   // [A0r0, A1r0, Br0, A0r1, A1r1, Br1][o]
    if (threadIdx.x < 32) {
        int o = threadIdx.x;
        sW[0][o] = nn1_w[2 * o];
        sW[1][o] = nn1_w[2 * o + 1];
        sW[2][o] = nn1_b[o];
        sW[3][o] = nn1_w[2 * (32 + o)];
        sW[4][o] = nn1_w[2 * (32 + o) + 1];
        sW[5][o] = nn1_b[32 + o];
    }
    __syncthreads();

    int t = blockIdx.x * blockDim.x + threadIdx.x;
    int e = t >> 3;
    int c = (t & 7) << 2;                 // channel base
    if (e >= N_EDGES) return;

    int src = __ldg(&ei[e]);
    int dst = __ldg(&ei[N_EDGES + e]);
    float2 a  = __ldg((const float2*)ea + e);
    float2 xs = __ldg((const float2*)x + src);

    float4 m;
    float* mp = &m.x;
#pragma unroll
    for (int j = 0; j < 4; j++) {
        int o = c + j;
        float w0 = fmaf(a.x, sW[0][o], fmaf(a.y, sW[1][o], sW[2][o]));
        float w1 = fmaf(a.x, sW[3][o], fmaf(a.y, sW[4][o], sW[5][o]));
        mp[j] = fmaf(xs.x, w0, xs.y * w1);
    }

    float* dptr = g_agg1 + dst * 32 + c;
    asm volatile("red.global.add.v4.f32 [%0], {%1, %2, %3, %4};"
                 :: "l"(dptr), "f"(m.x), "f"(m.y), "f"(m.z), "f"(m.w)
                 : "memory");
}

// ---------------------------------------------------------------------------
// Layer-2 edge scatter with vectorized atomics:
//   msg = a0*u0[src] + a1*u1[src] + u2[src]  (32 channels)
// 8 lanes per edge, each lane handles 4 channels via red.global.add.v4.f32
// ---------------------------------------------------------------------------
__global__ void edge2_kernel(const int*   __restrict__ ei,
                             const float* __restrict__ ea) {
    int t = blockIdx.x * blockDim.x + threadIdx.x;
    int e = t >> 3;
    int c = (t & 7) << 2;                 // channel base 0,4,...,28
    if (e >= N_EDGES) return;

    int src = __ldg(&ei[e]);
    int dst = __ldg(&ei[N_EDGES + e]);
    float2 a = __ldg((const float2*)ea + e);

    int base = src * 32 + c;
    float4 U0 = *(const float4*)(g_u0 + base);
    float4 U1 = *(const float4*)(g_u1 + base);
    float4 U2 = *(const float4*)(g_u2 + base);

    float4 m;
    m.x = fmaf(a.x, U0.x, fmaf(a.y, U1.x, U2.x));
    m.y = fmaf(a.x, U0.y, fmaf(a.y, U1.y, U2.y));
    m.z = fmaf(a.x, U0.z, fmaf(a.y, U1.z, U2.z));
    m.w = fmaf(a.x, U0.w, fmaf(a.y, U1.w, U2.w));

    float* dptr = g_agg2 + dst * 32 + c;
    asm volatile("red.global.add.v4.f32 [%0], {%1, %2, %3, %4};"
                 :: "l"(dptr), "f"(m.x), "f"(m.y), "f"(m.z), "f"(m.w)
                 : "memory");
}

// ---------------------------------------------------------------------------
// Layer-1 node update + layer-2 per-node precompute:
//   h1 = relu(agg1 + x@root1 + bias1)
//   u0 = h1 @ W0 ; u1 = h1 @ W1 ; u2 = h1 @ B   (from nn2_w/nn2_b)
// one warp per node, lane = channel o; h1 broadcast via shuffle
// ---------------------------------------------------------------------------
__global__ void node1_kernel(const float* __restrict__ x,
                             const float* __restrict__ root1,
                             const float* __restrict__ bias1,
                             const float* __restrict__ nn2_w,
                             const float* __restrict__ nn2_b) {
    __shared__ float sW[3][32][32];   // [k][i][o]  k=0:W0, 1:W1, 2:B
    for (int idx = threadIdx.x; idx < 1024; idx += blockDim.x) {
        int i = idx >> 5;
        int o = idx & 31;
        int row = i * 32 + o;             // row of nn2_w / nn2_b
        sW[0][i][o] = nn2_w[2 * row];
        sW[1][i][o] = nn2_w[2 * row + 1];
        sW[2][i][o] = nn2_b[row];
    }
    __syncthreads();

    int n = blockIdx.x * (blockDim.x >> 5) + (threadIdx.x >> 5);
    int o = threadIdx.x & 31;
    if (n >= N_NODES) return;

    float x0 = x[2 * n];
    float x1 = x[2 * n + 1];
    float h = g_agg1[n * 32 + o]
            + fmaf(x0, root1[o], fmaf(x1, root1[32 + o], bias1[o]));
    h = fmaxf(h, 0.0f);
    g_h1[n * 32 + o] = h;

    float u0 = 0.0f, u1 = 0.0f, u2 = 0.0f;
#pragma unroll
    for (int i = 0; i < 32; i++) {
        float hv = __shfl_sync(FULL, h, i);
        u0 = fmaf(hv, sW[0][i][o], u0);
        u1 = fmaf(hv, sW[1][i][o], u1);
        u2 = fmaf(hv, sW[2][i][o], u2);
    }
    g_u0[n * 32 + o] = u0;
    g_u1[n * 32 + o] = u1;
    g_u2[n * 32 + o] = u2;
}

// ---------------------------------------------------------------------------
// Tail: h2 = relu(agg2 + h1@root2 + bias2); h3 = relu(h2@fc1^T + b); out = h3@fc2^T + b
// one warp per node
// ---------------------------------------------------------------------------
__global__ void node2_kernel(const float* __restrict__ root2,
                             const float* __restrict__ bias2,
                             const float* __restrict__ fc1_w,
                             const float* __restrict__ fc1_b,
                             const float* __restrict__ fc2_w,
                             const float* __restrict__ fc2_b,
                             float* __restrict__ out) {
    __shared__ float sR[32][32];    // root2 [i][o]
    __shared__ float sF1[32][32];   // fc1_w transposed: [i][o] = fc1_w[o*32+i]
    __shared__ float sF2[32];
    __shared__ float sB2[32];
    __shared__ float sB1f[32];

    for (int idx = threadIdx.x; idx < 1024; idx += blockDim.x) {
        int i = idx >> 5;
        int o = idx & 31;
        sR[i][o]  = root2[i * 32 + o];
        sF1[i][o] = fc1_w[o * 32 + i];
    }
    if (threadIdx.x < 32) {
        sF2[threadIdx.x]  = fc2_w[threadIdx.x];
        sB2[threadIdx.x]  = bias2[threadIdx.x];
        sB1f[threadIdx.x] = fc1_b[threadIdx.x];
    }
    __syncthreads();

    int n = blockIdx.x * (blockDim.x >> 5) + (threadIdx.x >> 5);
    int o = threadIdx.x & 31;
    if (n >= N_NODES) return;

    float h1v = g_h1[n * 32 + o];
    float h2 = g_agg2[n * 32 + o] + sB2[o];
#pragma unroll
    for (int i = 0; i < 32; i++) {
        float hv = __shfl_sync(FULL, h1v, i);
        h2 = fmaf(hv, sR[i][o], h2);
    }
    h2 = fmaxf(h2, 0.0f);

    float h3 = sB1f[o];
#pragma unroll
    for (int i = 0; i < 32; i++) {
        float hv = __shfl_sync(FULL, h2, i);
        h3 = fmaf(hv, sF1[i][o], h3);
    }
    h3 = fmaxf(h3, 0.0f);

    float p = h3 * sF2[o];
#pragma unroll
    for (int off = 16; off > 0; off >>= 1)
        p += __shfl_xor_sync(FULL, p, off);
    if (o == 0)
        out[n] = p + fc2_b[0];
}

// ---------------------------------------------------------------------------
extern "C" void kernel_launch(void* const* d_in, const int* in_sizes, int n_in,
                              void* d_out, int out_size) {
    const float* x      = (const float*)d_in[0];
    const int*   ei     = (const int*)  d_in[1];
    const float* ea     = (const float*)d_in[2];
    const float* nn1_w  = (const float*)d_in[3];
    const float* nn1_b  = (const float*)d_in[4];
    const float* root1  = (const float*)d_in[5];
    const float* bias1  = (const float*)d_in[6];
    const float* nn2_w  = (const float*)d_in[7];
    const float* nn2_b  = (const float*)d_in[8];
    const float* root2  = (const float*)d_in[9];
    const float* bias2  = (const float*)d_in[10];
    const float* fc1_w  = (const float*)d_in[11];
    const float* fc1_b  = (const float*)d_in[12];
    const float* fc2_w  = (const float*)d_in[13];
    const float* fc2_b  = (const float*)d_in[14];
    float* out = (float*)d_out;

    const int TPB = 256;
    const int WARPS_PER_BLK = TPB / 32;

    zero_kernel<<<592, TPB>>>();

    // edge kernels: 8 lanes per edge -> N_EDGES*8 threads
    int ethreads = N_EDGES * 8;
    int eblocks = (ethreads + TPB - 1) / TPB;
    int nblocks = (N_NODES + WARPS_PER_BLK - 1) / WARPS_PER_BLK;

    edge1_kernel<<<eblocks, TPB>>>(x, ei, ea, nn1_w, nn1_b);
    node1_kernel<<<nblocks, TPB>>>(x, root1, bias1, nn2_w, nn2_b);
    edge2_kernel<<<eblocks, TPB>>>(ei, ea);
    node2_kernel<<<nblocks, TPB>>>(root2, bias2, fc1_w, fc1_b,
                                   fc2_w, fc2_b, out);
}

// round 7
// speedup vs baseline: 1.9290x; 1.5473x over previous
#include <cuda_runtime.h>

#define N_NODES 100000
#define N_EDGES 300000
#define FULL 0xffffffffu

// Scratch (device globals — no allocation allowed)
__device__ float g_agg1[N_NODES * 32];
__device__ float g_agg2[N_NODES * 32];
__device__ float g_h1  [N_NODES * 32];
__device__ float g_u0  [N_NODES * 32];
__device__ float g_u1  [N_NODES * 32];
__device__ float g_u2  [N_NODES * 32];

// ---------------------------------------------------------------------------
// Zero both aggregation buffers
// ---------------------------------------------------------------------------
__global__ void zero_kernel() {
    int idx = blockIdx.x * blockDim.x + threadIdx.x;
    int stride = gridDim.x * blockDim.x;
    const int total = N_NODES * 32;
    for (int i = idx; i < total; i += stride) {
        g_agg1[i] = 0.0f;
        g_agg2[i] = 0.0f;
    }
}

// ---------------------------------------------------------------------------
// Layer-1 edge scatter, weights in shared (x is only 2-dim so compute direct):
// 8 lanes per edge, 4 channels per lane, red.global.add.v4.f32 scatter.
// ---------------------------------------------------------------------------
__global__ void edge1_kernel(const float* __restrict__ x,
                             const int*   __restrict__ ei,
                             const float* __restrict__ ea,
                             const float* __restrict__ nn1_w,
                             const float* __restrict__ nn1_b) {
    __shared__ float sW[6][32];   // [A0r0, A1r0, Br0, A0r1, A1r1, Br1][o]
    if (threadIdx.x < 32) {
        int o = threadIdx.x;
        sW[0][o] = nn1_w[2 * o];
        sW[1][o] = nn1_w[2 * o + 1];
        sW[2][o] = nn1_b[o];
        sW[3][o] = nn1_w[2 * (32 + o)];
        sW[4][o] = nn1_w[2 * (32 + o) + 1];
        sW[5][o] = nn1_b[32 + o];
    }
    __syncthreads();

    int t = blockIdx.x * blockDim.x + threadIdx.x;
    int e = t >> 3;
    int c = (t & 7) << 2;                 // channel base
    if (e >= N_EDGES) return;

    int src = __ldg(&ei[e]);
    int dst = __ldg(&ei[N_EDGES + e]);
    float2 a  = __ldg((const float2*)ea + e);
    float2 xs = __ldg((const float2*)x + src);

    float4 m;
    float* mp = &m.x;
#pragma unroll
    for (int j = 0; j < 4; j++) {
        int o = c + j;
        float w0 = fmaf(a.x, sW[0][o], fmaf(a.y, sW[1][o], sW[2][o]));
        float w1 = fmaf(a.x, sW[3][o], fmaf(a.y, sW[4][o], sW[5][o]));
        mp[j] = fmaf(xs.x, w0, xs.y * w1);
    }

    float* dptr = g_agg1 + dst * 32 + c;
    asm volatile("red.global.add.v4.f32 [%0], {%1, %2, %3, %4};"
                 :: "l"(dptr), "f"(m.x), "f"(m.y), "f"(m.z), "f"(m.w)
                 : "memory");
}

// ---------------------------------------------------------------------------
// Layer-2 edge scatter with vectorized atomics:
//   msg = a0*u0[src] + a1*u1[src] + u2[src]  (32 channels)
// ---------------------------------------------------------------------------
__global__ void edge2_kernel(const int*   __restrict__ ei,
                             const float* __restrict__ ea) {
    int t = blockIdx.x * blockDim.x + threadIdx.x;
    int e = t >> 3;
    int c = (t & 7) << 2;                 // channel base 0,4,...,28
    if (e >= N_EDGES) return;

    int src = __ldg(&ei[e]);
    int dst = __ldg(&ei[N_EDGES + e]);
    float2 a = __ldg((const float2*)ea + e);

    int base = src * 32 + c;
    float4 U0 = *(const float4*)(g_u0 + base);
    float4 U1 = *(const float4*)(g_u1 + base);
    float4 U2 = *(const float4*)(g_u2 + base);

    float4 m;
    m.x = fmaf(a.x, U0.x, fmaf(a.y, U1.x, U2.x));
    m.y = fmaf(a.x, U0.y, fmaf(a.y, U1.y, U2.y));
    m.z = fmaf(a.x, U0.z, fmaf(a.y, U1.z, U2.z));
    m.w = fmaf(a.x, U0.w, fmaf(a.y, U1.w, U2.w));

    float* dptr = g_agg2 + dst * 32 + c;
    asm volatile("red.global.add.v4.f32 [%0], {%1, %2, %3, %4};"
                 :: "l"(dptr), "f"(m.x), "f"(m.y), "f"(m.z), "f"(m.w)
                 : "memory");
}

// ---------------------------------------------------------------------------
// Layer-1 node update + layer-2 per-node precompute, REGISTER-resident weights.
//   h1 = relu(agg1 + x@root1 + bias1)
//   u0 = h1 @ W0 ; u1 = h1 @ W1 ; u2 = h1 @ B   (from nn2_w/nn2_b)
// One warp per node, lane = channel o; each lane holds column o of W0/W1/B
// in registers; warp grid-strides over nodes so the load amortizes.
// ---------------------------------------------------------------------------
__global__ void __launch_bounds__(256) node1_kernel(
                             const float* __restrict__ x,
                             const float* __restrict__ root1,
                             const float* __restrict__ bias1,
                             const float* __restrict__ nn2_w,
                             const float* __restrict__ nn2_b) {
    int o = threadIdx.x & 31;

    float W0[32], W1[32], B[32];
#pragma unroll
    for (int i = 0; i < 32; i++) {
        int row = i * 32 + o;
        float2 w = __ldg((const float2*)nn2_w + row);   // (W0,W1) interleaved
        W0[i] = w.x;
        W1[i] = w.y;
        B[i]  = __ldg(&nn2_b[row]);
    }
    float r1a = __ldg(&root1[o]);
    float r1b = __ldg(&root1[32 + o]);
    float b1  = __ldg(&bias1[o]);

    int warp  = blockIdx.x * (blockDim.x >> 5) + (threadIdx.x >> 5);
    int nwarp = gridDim.x * (blockDim.x >> 5);

    for (int n = warp; n < N_NODES; n += nwarp) {
        float2 xs = __ldg((const float2*)x + n);
        float h = g_agg1[n * 32 + o]
                + fmaf(xs.x, r1a, fmaf(xs.y, r1b, b1));
        h = fmaxf(h, 0.0f);
        g_h1[n * 32 + o] = h;

        float u0 = 0.0f, u1 = 0.0f, u2 = 0.0f;
#pragma unroll
        for (int i = 0; i < 32; i++) {
            float hv = __shfl_sync(FULL, h, i);
            u0 = fmaf(hv, W0[i], u0);
            u1 = fmaf(hv, W1[i], u1);
            u2 = fmaf(hv, B[i],  u2);
        }
        g_u0[n * 32 + o] = u0;
        g_u1[n * 32 + o] = u1;
        g_u2[n * 32 + o] = u2;
    }
}

// ---------------------------------------------------------------------------
// Tail with REGISTER-resident weights:
//   h2 = relu(agg2 + h1@root2 + bias2); h3 = relu(h2@fc1^T + b1f); out = h3.fc2 + b
// One warp per node, grid-stride.
// ---------------------------------------------------------------------------
__global__ void __launch_bounds__(256) node2_kernel(
                             const float* __restrict__ root2,
                             const float* __restrict__ bias2,
                             const float* __restrict__ fc1_w,
                             const float* __restrict__ fc1_b,
                             const float* __restrict__ fc2_w,
                             const float* __restrict__ fc2_b,
                             float* __restrict__ out) {
    int o = threadIdx.x & 31;

    float R[32], F1[32];
#pragma unroll
    for (int i = 0; i < 32; i++)
        R[i] = __ldg(&root2[i * 32 + o]);    // column o of root2
    // lane o needs row o of fc1_w (consecutive) -> load as 8 float4
#pragma unroll
    for (int q = 0; q < 8; q++) {
        float4 v = __ldg((const float4*)(fc1_w + o * 32) + q);
        F1[4 * q + 0] = v.x;
        F1[4 * q + 1] = v.y;
        F1[4 * q + 2] = v.z;
        F1[4 * q + 3] = v.w;
    }
    float b2  = __ldg(&bias2[o]);
    float b1f = __ldg(&fc1_b[o]);
    float f2  = __ldg(&fc2_w[o]);
    float f2b = __ldg(&fc2_b[0]);

    int warp  = blockIdx.x * (blockDim.x >> 5) + (threadIdx.x >> 5);
    int nwarp = gridDim.x * (blockDim.x >> 5);

    for (int n = warp; n < N_NODES; n += nwarp) {
        float h1v = g_h1[n * 32 + o];
        float h2  = g_agg2[n * 32 + o] + b2;
#pragma unroll
        for (int i = 0; i < 32; i++) {
            float hv = __shfl_sync(FULL, h1v, i);
            h2 = fmaf(hv, R[i], h2);
        }
        h2 = fmaxf(h2, 0.0f);

        // h3[o] = relu(sum_i h2[i] * fc1_w[o][i] + fc1_b[o])
        float h3 = b1f;
#pragma unroll
        for (int i = 0; i < 32; i++) {
            float hv = __shfl_sync(FULL, h2, i);
            h3 = fmaf(hv, F1[i], h3);
        }
        h3 = fmaxf(h3, 0.0f);

        float p = h3 * f2;
#pragma unroll
        for (int off = 16; off > 0; off >>= 1)
            p += __shfl_xor_sync(FULL, p, off);
        if (o == 0)
            out[n] = p + f2b;
    }
}

// ---------------------------------------------------------------------------
extern "C" void kernel_launch(void* const* d_in, const int* in_sizes, int n_in,
                              void* d_out, int out_size) {
    const float* x      = (const float*)d_in[0];
    const int*   ei     = (const int*)  d_in[1];
    const float* ea     = (const float*)d_in[2];
    const float* nn1_w  = (const float*)d_in[3];
    const float* nn1_b  = (const float*)d_in[4];
    const float* root1  = (const float*)d_in[5];
    const float* bias1  = (const float*)d_in[6];
    const float* nn2_w  = (const float*)d_in[7];
    const float* nn2_b  = (const float*)d_in[8];
    const float* root2  = (const float*)d_in[9];
    const float* bias2  = (const float*)d_in[10];
    const float* fc1_w  = (const float*)d_in[11];
    const float* fc1_b  = (const float*)d_in[12];
    const float* fc2_w  = (const float*)d_in[13];
    const float* fc2_b  = (const float*)d_in[14];
    float* out = (float*)d_out;

    const int TPB = 256;

    zero_kernel<<<592, TPB>>>();

    int ethreads = N_EDGES * 8;
    int eblocks = (ethreads + TPB - 1) / TPB;

    edge1_kernel<<<eblocks, TPB>>>(x, ei, ea, nn1_w, nn1_b);
    // grid-stride node kernels: enough warps for 2 waves at reduced occupancy
    node1_kernel<<<592, TPB>>>(x, root1, bias1, nn2_w, nn2_b);
    edge2_kernel<<<eblocks, TPB>>>(ei, ea);
    node2_kernel<<<592, TPB>>>(root2, bias2, fc1_w, fc1_b,
                               fc2_w, fc2_b, out);
}

// round 8
// speedup vs baseline: 2.2697x; 1.1766x over previous
#include <cuda_runtime.h>

#define N_NODES 100000
#define N_EDGES 300000
#define FULL 0xffffffffu

// Scratch (device globals — no allocation allowed)
__device__ float g_agg1[N_NODES * 32];
__device__ float g_agg2[N_NODES * 32];
__device__ float g_u0  [N_NODES * 32];
__device__ float g_u1  [N_NODES * 32];
__device__ float g_u2  [N_NODES * 32];

// ---------------------------------------------------------------------------
// Pre: initialize agg1 with the root term of layer 1:
//   agg1[n,o] = x[n,0]*root1[0,o] + x[n,1]*root1[1,o] + bias1[o]
// (edge1 atomics then accumulate on top; sums commute)
// ---------------------------------------------------------------------------
__global__ void pre_kernel(const float* __restrict__ x,
                           const float* __restrict__ root1,
                           const float* __restrict__ bias1) {
    int idx = blockIdx.x * blockDim.x + threadIdx.x;
    int stride = gridDim.x * blockDim.x;
    const int total = N_NODES * 32;
    for (int i = idx; i < total; i += stride) {
        int n = i >> 5;
        int o = i & 31;
        float2 xs = __ldg((const float2*)x + n);
        g_agg1[i] = fmaf(xs.x, __ldg(&root1[o]),
                    fmaf(xs.y, __ldg(&root1[32 + o]), __ldg(&bias1[o])));
    }
}

// ---------------------------------------------------------------------------
// Layer-1 edge scatter, weights in shared (x is only 2-dim so compute direct):
// 8 lanes per edge, 4 channels per lane, red.global.add.v4.f32 scatter.
// ---------------------------------------------------------------------------
__global__ void edge1_kernel(const float* __restrict__ x,
                             const int*   __restrict__ ei,
                             const float* __restrict__ ea,
                             const float* __restrict__ nn1_w,
                             const float* __restrict__ nn1_b) {
    __shared__ float sW[6][32];   // [A0r0, A1r0, Br0, A0r1, A1r1, Br1][o]
    if (threadIdx.x < 32) {
        int o = threadIdx.x;
        sW[0][o] = nn1_w[2 * o];
        sW[1][o] = nn1_w[2 * o + 1];
        sW[2][o] = nn1_b[o];
        sW[3][o] = nn1_w[2 * (32 + o)];
        sW[4][o] = nn1_w[2 * (32 + o) + 1];
        sW[5][o] = nn1_b[32 + o];
    }
    __syncthreads();

    int t = blockIdx.x * blockDim.x + threadIdx.x;
    int e = t >> 3;
    int c = (t & 7) << 2;                 // channel base
    if (e >= N_EDGES) return;

    int src = __ldg(&ei[e]);
    int dst = __ldg(&ei[N_EDGES + e]);
    float2 a  = __ldg((const float2*)ea + e);
    float2 xs = __ldg((const float2*)x + src);

    float4 m;
    float* mp = &m.x;
#pragma unroll
    for (int j = 0; j < 4; j++) {
        int o = c + j;
        float w0 = fmaf(a.x, sW[0][o], fmaf(a.y, sW[1][o], sW[2][o]));
        float w1 = fmaf(a.x, sW[3][o], fmaf(a.y, sW[4][o], sW[5][o]));
        mp[j] = fmaf(xs.x, w0, xs.y * w1);
    }

    float* dptr = g_agg1 + dst * 32 + c;
    asm volatile("red.global.add.v4.f32 [%0], {%1, %2, %3, %4};"
                 :: "l"(dptr), "f"(m.x), "f"(m.y), "f"(m.z), "f"(m.w)
                 : "memory");
}

// ---------------------------------------------------------------------------
// Layer-2 edge scatter with vectorized atomics:
//   msg = a0*u0[src] + a1*u1[src] + u2[src]  (32 channels)
// NOTE: g_agg2 is pre-initialized by node1 with h1@root2 + bias2.
// ---------------------------------------------------------------------------
__global__ void edge2_kernel(const int*   __restrict__ ei,
                             const float* __restrict__ ea) {
    int t = blockIdx.x * blockDim.x + threadIdx.x;
    int e = t >> 3;
    int c = (t & 7) << 2;                 // channel base 0,4,...,28
    if (e >= N_EDGES) return;

    int src = __ldg(&ei[e]);
    int dst = __ldg(&ei[N_EDGES + e]);
    float2 a = __ldg((const float2*)ea + e);

    int base = src * 32 + c;
    float4 U0 = *(const float4*)(g_u0 + base);
    float4 U1 = *(const float4*)(g_u1 + base);
    float4 U2 = *(const float4*)(g_u2 + base);

    float4 m;
    m.x = fmaf(a.x, U0.x, fmaf(a.y, U1.x, U2.x));
    m.y = fmaf(a.x, U0.y, fmaf(a.y, U1.y, U2.y));
    m.z = fmaf(a.x, U0.z, fmaf(a.y, U1.z, U2.z));
    m.w = fmaf(a.x, U0.w, fmaf(a.y, U1.w, U2.w));

    float* dptr = g_agg2 + dst * 32 + c;
    asm volatile("red.global.add.v4.f32 [%0], {%1, %2, %3, %4};"
                 :: "l"(dptr), "f"(m.x), "f"(m.y), "f"(m.z), "f"(m.w)
                 : "memory");
}

// ---------------------------------------------------------------------------
// Layer-1 node update + layer-2 per-node precompute, REGISTER-resident weights.
//   h1 = relu(agg1)                       (root term already folded in by pre)
//   u0 = h1 @ W0 ; u1 = h1 @ W1 ; u2 = h1 @ B    (from nn2_w/nn2_b)
//   agg2[n] = h1 @ root2 + bias2          (initializer for edge2 atomics)
// One warp per node, lane = channel o; lane holds column o of W0/W1/B/root2
// in registers; warp grid-strides over nodes. One shuffle feeds 4 FMAs.
// ---------------------------------------------------------------------------
__global__ void __launch_bounds__(256) node1_kernel(
                             const float* __restrict__ nn2_w,
                             const float* __restrict__ nn2_b,
                             const float* __restrict__ root2,
                             const float* __restrict__ bias2) {
    int o = threadIdx.x & 31;

    float W0[32], W1[32], B[32], R2[32];
#pragma unroll
    for (int i = 0; i < 32; i++) {
        int row = i * 32 + o;
        float2 w = __ldg((const float2*)nn2_w + row);   // (W0,W1) interleaved
        W0[i] = w.x;
        W1[i] = w.y;
        B[i]  = __ldg(&nn2_b[row]);
        R2[i] = __ldg(&root2[row]);
    }
    float b2 = __ldg(&bias2[o]);

    int warp  = blockIdx.x * (blockDim.x >> 5) + (threadIdx.x >> 5);
    int nwarp = gridDim.x * (blockDim.x >> 5);

    for (int n = warp; n < N_NODES; n += nwarp) {
        float h = fmaxf(g_agg1[n * 32 + o], 0.0f);

        float u0 = 0.0f, u1 = 0.0f, u2 = 0.0f, r2 = b2;
#pragma unroll
        for (int i = 0; i < 32; i++) {
            float hv = __shfl_sync(FULL, h, i);
            u0 = fmaf(hv, W0[i], u0);
            u1 = fmaf(hv, W1[i], u1);
            u2 = fmaf(hv, B[i],  u2);
            r2 = fmaf(hv, R2[i], r2);
        }
        g_u0[n * 32 + o] = u0;
        g_u1[n * 32 + o] = u1;
        g_u2[n * 32 + o] = u2;
        g_agg2[n * 32 + o] = r2;
    }
}

// ---------------------------------------------------------------------------
// Tail with REGISTER-resident weights (root2 term already folded into agg2):
//   h2 = relu(agg2); h3 = relu(h2@fc1^T + b1f); out = h3.fc2 + b
// One warp per node, grid-stride.
// ---------------------------------------------------------------------------
__global__ void __launch_bounds__(256) node2_kernel(
                             const float* __restrict__ fc1_w,
                             const float* __restrict__ fc1_b,
                             const float* __restrict__ fc2_w,
                             const float* __restrict__ fc2_b,
                             float* __restrict__ out) {
    int o = threadIdx.x & 31;

    float F1[32];
    // lane o needs row o of fc1_w (consecutive) -> load as 8 float4
#pragma unroll
    for (int q = 0; q < 8; q++) {
        float4 v = __ldg((const float4*)(fc1_w + o * 32) + q);
        F1[4 * q + 0] = v.x;
        F1[4 * q + 1] = v.y;
        F1[4 * q + 2] = v.z;
        F1[4 * q + 3] = v.w;
    }
    float b1f = __ldg(&fc1_b[o]);
    float f2  = __ldg(&fc2_w[o]);
    float f2b = __ldg(&fc2_b[0]);

    int warp  = blockIdx.x * (blockDim.x >> 5) + (threadIdx.x >> 5);
    int nwarp = gridDim.x * (blockDim.x >> 5);

    for (int n = warp; n < N_NODES; n += nwarp) {
        float h2 = fmaxf(g_agg2[n * 32 + o], 0.0f);

        // h3[o] = relu(sum_i h2[i] * fc1_w[o][i] + fc1_b[o])
        float h3 = b1f;
#pragma unroll
        for (int i = 0; i < 32; i++) {
            float hv = __shfl_sync(FULL, h2, i);
            h3 = fmaf(hv, F1[i], h3);
        }
        h3 = fmaxf(h3, 0.0f);

        float p = h3 * f2;
#pragma unroll
        for (int off = 16; off > 0; off >>= 1)
            p += __shfl_xor_sync(FULL, p, off);
        if (o == 0)
            out[n] = p + f2b;
    }
}

// ---------------------------------------------------------------------------
extern "C" void kernel_launch(void* const* d_in, const int* in_sizes, int n_in,
                              void* d_out, int out_size) {
    const float* x      = (const float*)d_in[0];
    const int*   ei     = (const int*)  d_in[1];
    const float* ea     = (const float*)d_in[2];
    const float* nn1_w  = (const float*)d_in[3];
    const float* nn1_b  = (const float*)d_in[4];
    const float* root1  = (const float*)d_in[5];
    const float* bias1  = (const float*)d_in[6];
    const float* nn2_w  = (const float*)d_in[7];
    const float* nn2_b  = (const float*)d_in[8];
    const float* root2  = (const float*)d_in[9];
    const float* bias2  = (const float*)d_in[10];
    const float* fc1_w  = (const float*)d_in[11];
    const float* fc1_b  = (const float*)d_in[12];
    const float* fc2_w  = (const float*)d_in[13];
    const float* fc2_b  = (const float*)d_in[14];
    float* out = (float*)d_out;

    const int TPB = 256;

    pre_kernel<<<592, TPB>>>(x, root1, bias1);

    int ethreads = N_EDGES * 8;
    int eblocks = (ethreads + TPB - 1) / TPB;

    edge1_kernel<<<eblocks, TPB>>>(x, ei, ea, nn1_w, nn1_b);
    node1_kernel<<<592, TPB>>>(nn2_w, nn2_b, root2, bias2);
    edge2_kernel<<<eblocks, TPB>>>(ei, ea);
    node2_kernel<<<592, TPB>>>(fc1_w, fc1_b, fc2_w, fc2_b, out);
}

// round 17
// speedup vs baseline: 2.7637x; 1.2177x over previous
#include <cuda_runtime.h>
#include <cstdint>

#define N_NODES 100000
#define N_EDGES 300000
#define FULL 0xffffffffu

// Scratch (device globals — no allocation allowed)
__device__ float g_agg1[N_NODES * 32];
__device__ float g_agg2[N_NODES * 32];
__device__ float g_u0  [N_NODES * 32];
__device__ float g_u1  [N_NODES * 32];
__device__ float g_u2  [N_NODES * 32];

// ---- f32x2 packed helpers (sm_10x FFMA2 path; ptxas never auto-fuses) ------
__device__ __forceinline__ unsigned long long pack2(float lo, float hi) {
    unsigned long long r;
    asm("mov.b64 %0, {%1, %2};" : "=l"(r) : "f"(lo), "f"(hi));
    return r;
}
__device__ __forceinline__ void unpack2(unsigned long long v, float& lo, float& hi) {
    asm("mov.b64 {%0, %1}, %2;" : "=f"(lo), "=f"(hi) : "l"(v));
}
__device__ __forceinline__ unsigned long long fma2(unsigned long long a,
                                                   unsigned long long b,
                                                   unsigned long long c) {
    unsigned long long d;
    asm("fma.rn.f32x2 %0, %1, %2, %3;" : "=l"(d) : "l"(a), "l"(b), "l"(c));
    return d;
}

// ---------------------------------------------------------------------------
// Pre: initialize agg1 with the root term of layer 1:
//   agg1[n,o] = x[n,0]*root1[0,o] + x[n,1]*root1[1,o] + bias1[o]
// ---------------------------------------------------------------------------
__global__ void pre_kernel(const float* __restrict__ x,
                           const float* __restrict__ root1,
                           const float* __restrict__ bias1) {
    int idx = blockIdx.x * blockDim.x + threadIdx.x;
    int stride = gridDim.x * blockDim.x;
    const int total = N_NODES * 32;
    for (int i = idx; i < total; i += stride) {
        int n = i >> 5;
        int o = i & 31;
        float2 xs = __ldg((const float2*)x + n);
        g_agg1[i] = fmaf(xs.x, __ldg(&root1[o]),
                    fmaf(xs.y, __ldg(&root1[32 + o]), __ldg(&bias1[o])));
    }
}

// ---------------------------------------------------------------------------
// Layer-1 edge scatter, weights in shared; v4-red scatter. (unchanged)
// ---------------------------------------------------------------------------
__global__ void edge1_kernel(const float* __restrict__ x,
                             const int*   __restrict__ ei,
                             const float* __restrict__ ea,
                             const float* __restrict__ nn1_w,
                             const float* __restrict__ nn1_b) {
    __shared__ float sW[6][32];
    if (threadIdx.x < 32) {
        int o = threadIdx.x;
        sW[0][o] = nn1_w[2 * o];
        sW[1][o] = nn1_w[2 * o + 1];
        sW[2][o] = nn1_b[o];
        sW[3][o] = nn1_w[2 * (32 + o)];
        sW[4][o] = nn1_w[2 * (32 + o) + 1];
        sW[5][o] = nn1_b[32 + o];
    }
    __syncthreads();

    int t = blockIdx.x * blockDim.x + threadIdx.x;
    int e = t >> 3;
    int c = (t & 7) << 2;
    if (e >= N_EDGES) return;

    int src = __ldg(&ei[e]);
    int dst = __ldg(&ei[N_EDGES + e]);
    float2 a  = __ldg((const float2*)ea + e);
    float2 xs = __ldg((const float2*)x + src);

    float4 m;
    float* mp = &m.x;
#pragma unroll
    for (int j = 0; j < 4; j++) {
        int o = c + j;
        float w0 = fmaf(a.x, sW[0][o], fmaf(a.y, sW[1][o], sW[2][o]));
        float w1 = fmaf(a.x, sW[3][o], fmaf(a.y, sW[4][o], sW[5][o]));
        mp[j] = fmaf(xs.x, w0, xs.y * w1);
    }

    float* dptr = g_agg1 + dst * 32 + c;
    asm volatile("red.global.add.v4.f32 [%0], {%1, %2, %3, %4};"
                 :: "l"(dptr), "f"(m.x), "f"(m.y), "f"(m.z), "f"(m.w)
                 : "memory");
}

// ---------------------------------------------------------------------------
// Layer-2 edge scatter (unchanged). g_agg2 pre-initialized by node1.
// ---------------------------------------------------------------------------
__global__ void edge2_kernel(const int*   __restrict__ ei,
                             const float* __restrict__ ea) {
    int t = blockIdx.x * blockDim.x + threadIdx.x;
    int e = t >> 3;
    int c = (t & 7) << 2;
    if (e >= N_EDGES) return;

    int src = __ldg(&ei[e]);
    int dst = __ldg(&ei[N_EDGES + e]);
    float2 a = __ldg((const float2*)ea + e);

    int base = src * 32 + c;
    float4 U0 = *(const float4*)(g_u0 + base);
    float4 U1 = *(const float4*)(g_u1 + base);
    float4 U2 = *(const float4*)(g_u2 + base);

    float4 m;
    m.x = fmaf(a.x, U0.x, fmaf(a.y, U1.x, U2.x));
    m.y = fmaf(a.x, U0.y, fmaf(a.y, U1.y, U2.y));
    m.z = fmaf(a.x, U0.z, fmaf(a.y, U1.z, U2.z));
    m.w = fmaf(a.x, U0.w, fmaf(a.y, U1.w, U2.w));

    float* dptr = g_agg2 + dst * 32 + c;
    asm volatile("red.global.add.v4.f32 [%0], {%1, %2, %3, %4};"
                 :: "l"(dptr), "f"(m.x), "f"(m.y), "f"(m.z), "f"(m.w)
                 : "memory");
}

// ---------------------------------------------------------------------------
// node1 with packed-f32x2 weights + next-node prefetch:
//   h1 = relu(agg1)
//   (u0,u1) += h1 * (W0,W1) ; (u2,r2) += h1 * (B,root2)   [FFMA2]
//   agg2[n]  = r2 + bias2   (init for edge2 atomics)
// ---------------------------------------------------------------------------
__global__ void __launch_bounds__(256) node1_kernel(
                             const float* __restrict__ nn2_w,
                             const float* __restrict__ nn2_b,
                             const float* __restrict__ root2,
                             const float* __restrict__ bias2) {
    int o = threadIdx.x & 31;

    unsigned long long WP01[32], WP23[32];
#pragma unroll
    for (int i = 0; i < 32; i++) {
        int row = i * 32 + o;
        float2 w = __ldg((const float2*)nn2_w + row);    // (W0,W1)
        WP01[i] = pack2(w.x, w.y);
        WP23[i] = pack2(__ldg(&nn2_b[row]), __ldg(&root2[row]));
    }
    float b2 = __ldg(&bias2[o]);

    int warp  = blockIdx.x * (blockDim.x >> 5) + (threadIdx.x >> 5);
    int nwarp = gridDim.x * (blockDim.x >> 5);
    if (warp >= N_NODES) return;

    float cur = g_agg1[warp * 32 + o];
    for (int n = warp; n < N_NODES; n += nwarp) {
        float h = fmaxf(cur, 0.0f);
        int n2 = n + nwarp;
        if (n2 < N_NODES) cur = g_agg1[n2 * 32 + o];   // prefetch next

        unsigned long long acc01 = 0ull;                // (0,0)
        unsigned long long acc23 = pack2(0.0f, b2);     // (u2, r2)
#pragma unroll
        for (int i = 0; i < 32; i++) {
            float hv = __shfl_sync(FULL, h, i);
            unsigned long long hvv = pack2(hv, hv);
            acc01 = fma2(hvv, WP01[i], acc01);
            acc23 = fma2(hvv, WP23[i], acc23);
        }
        float u0, u1, u2, r2;
        unpack2(acc01, u0, u1);
        unpack2(acc23, u2, r2);
        g_u0[n * 32 + o] = u0;
        g_u1[n * 32 + o] = u1;
        g_u2[n * 32 + o] = u2;
        g_agg2[n * 32 + o] = r2;
    }
}

// ---------------------------------------------------------------------------
// node2 tail with prefetch:
//   h2 = relu(agg2); h3 = relu(h2@fc1^T + b1f); out = h3.fc2 + b
// ---------------------------------------------------------------------------
__global__ void __launch_bounds__(256) node2_kernel(
                             const float* __restrict__ fc1_w,
                             const float* __restrict__ fc1_b,
                             const float* __restrict__ fc2_w,
                             const float* __restrict__ fc2_b,
                             float* __restrict__ out) {
    int o = threadIdx.x & 31;

    float F1[32];
#pragma unroll
    for (int q = 0; q < 8; q++) {
        float4 v = __ldg((const float4*)(fc1_w + o * 32) + q);
        F1[4 * q + 0] = v.x;
        F1[4 * q + 1] = v.y;
        F1[4 * q + 2] = v.z;
        F1[4 * q + 3] = v.w;
    }
    float b1f = __ldg(&fc1_b[o]);
    float f2  = __ldg(&fc2_w[o]);
    float f2b = __ldg(&fc2_b[0]);

    int warp  = blockIdx.x * (blockDim.x >> 5) + (threadIdx.x >> 5);
    int nwarp = gridDim.x * (blockDim.x >> 5);
    if (warp >= N_NODES) return;

    float cur = g_agg2[warp * 32 + o];
    for (int n = warp; n < N_NODES; n += nwarp) {
        float h2 = fmaxf(cur, 0.0f);
        int n2 = n + nwarp;
        if (n2 < N_NODES) cur = g_agg2[n2 * 32 + o];   // prefetch next

        float h3 = b1f;
#pragma unroll
        for (int i = 0; i < 32; i++) {
            float hv = __shfl_sync(FULL, h2, i);
            h3 = fmaf(hv, F1[i], h3);
        }
        h3 = fmaxf(h3, 0.0f);

        float p = h3 * f2;
#pragma unroll
        for (int off = 16; off > 0; off >>= 1)
            p += __shfl_xor_sync(FULL, p, off);
        if (o == 0)
            out[n] = p + f2b;
    }
}

// ---------------------------------------------------------------------------
extern "C" void kernel_launch(void* const* d_in, const int* in_sizes, int n_in,
                              void* d_out, int out_size) {
    const float* x      = (const float*)d_in[0];
    const int*   ei     = (const int*)  d_in[1];
    const float* ea     = (const float*)d_in[2];
    const float* nn1_w  = (const float*)d_in[3];
    const float* nn1_b  = (const float*)d_in[4];
    const float* root1  = (const float*)d_in[5];
    const float* bias1  = (const float*)d_in[6];
    const float* nn2_w  = (const float*)d_in[7];
    const float* nn2_b  = (const float*)d_in[8];
    const float* root2  = (const float*)d_in[9];
    const float* bias2  = (const float*)d_in[10];
    const float* fc1_w  = (const float*)d_in[11];
    const float* fc1_b  = (const float*)d_in[12];
    const float* fc2_w  = (const float*)d_in[13];
    const float* fc2_b  = (const float*)d_in[14];
    float* out = (float*)d_out;

    const int TPB = 256;

    pre_kernel<<<592, TPB>>>(x, root1, bias1);

    int ethreads = N_EDGES * 8;
    int eblocks = (ethreads + TPB - 1) / TPB;

    edge1_kernel<<<eblocks, TPB>>>(x, ei, ea, nn1_w, nn1_b);
    node1_kernel<<<592, TPB>>>(nn2_w, nn2_b, root2, bias2);
    edge2_kernel<<<eblocks, TPB>>>(ei, ea);
    node2_kernel<<<592, TPB>>>(fc1_w, fc1_b, fc2_w, fc2_b, out);
}